// round 14
// baseline (speedup 1.0000x reference)
#include <cuda_runtime.h>
#include <cuda_fp16.h>
#include <math.h>

// Problem constants
#define BB    4
#define KDIM  128
#define V_IN  256
#define E_IN  512
#define E_OUT 512
#define V_OUT 256
#define P_PE  200
#define T_PE  100
#define NROWS (BB*KDIM)        // 512
#define M_BIG (BB*KDIM*KDIM)   // 65536

// Scratch (device globals -- allocation-free per harness rules)
__device__ float  g_v[NROWS*V_IN];
__device__ float  g_q[NROWS*E_OUT];
__device__ float  g_k[NROWS*E_OUT];
__device__ float  g_self[NROWS*E_OUT];
__device__ float  g_v2[NROWS*E_OUT];
__device__ float  g_pool[BB*E_OUT];

// fp16-at-rest GEMM operands
__device__ __half g_vh[NROWS*V_IN];
__device__ __half g_efh[(size_t)M_BIG*E_IN];     // e_f as half (67 MB)
__device__ __half g_eh [(size_t)M_BIG*E_IN];     // silu(epe) half
__device__ __half g_hh [(size_t)M_BIG*E_OUT];    // silu(ev1) half
__device__ __half g_tpeh[BB*128];                // t_pe padded to 128
__device__ __half g_wepeh[640*512];              // W_epe padded 612->640 rows
__device__ __half g_wev1h[1024*512];
__device__ __half g_wev2h[512*512];

__device__ __forceinline__ float siluf(float x){ return x / (1.f + __expf(-x)); }
__device__ __forceinline__ float sigmf(float x){ return 1.f / (1.f + __expf(-x)); }

__device__ __forceinline__ unsigned smem_u32(const void* p){
    unsigned r;
    asm("{ .reg .u64 t; cvta.to.shared.u64 t, %1; cvt.u32.u64 %0, t; }" : "=r"(r) : "l"(p));
    return r;
}
__device__ __forceinline__ void cp16(unsigned dst, const void* src){
    asm volatile("cp.async.cg.shared.global [%0], [%1], 16;" :: "r"(dst), "l"(src) : "memory");
}
#define CP_COMMIT() asm volatile("cp.async.commit_group;" ::: "memory")
#define CP_WAIT2()  asm volatile("cp.async.wait_group 2;" ::: "memory")

// ===========================================================================
// FP16 mma.sync GEMM, fp16-at-rest, 4-stage cp.async pipeline.
// CTA tile 128x128, 512 threads = 16 warps (4x4), warp tile 32x32.
// __launch_bounds__(512,2) -> 64 regs/thread -> 2 CTAs/SM = 32 WARPS/SM.
// One barrier per stage; cp issue overlaps compute.
// MODE 0 (epe): A = [g_efh(512)|g_tpeh(128 pad)], KD=612(->640), silu, half out
// MODE 1 (ev1): A = [v_i(256)|v_j(256)|g_eh(512)], KD=1024, silu, half out
// MODE 2 (ev2): A = g_hh, KD=512, no act, fp32 out
// ===========================================================================
#define ASTRIDE 40                       // halves per A smem row (80B)
#define BSTRIDE 136                      // halves per B smem row (272B)
#define ABYTES (128*ASTRIDE*2)           // 10240 B per A stage
#define BBYTES (32*BSTRIDE*2)            // 8704 B per B stage
#define NSTAGE 4
#define SMEM_SZ (NSTAGE*(ABYTES+BBYTES)) // 75776 B

template<int MODE>
__device__ __forceinline__ const __half* srcA(int m, int k,
                                              const __half* __restrict__ A0,
                                              const __half* __restrict__ A1,
                                              int b_batch, int i_idx)
{
    if (MODE == 0) {
        return (k < 512) ? A0 + (size_t)m*512 + k
                         : A1 + b_batch*128 + (k - 512);
    } else if (MODE == 1) {
        if (k < 256) return A0 + ((b_batch<<7) + i_idx)*256 + k;
        if (k < 512) return A0 + ((b_batch<<7) + (m & 127))*256 + (k - 256);
        return A1 + (size_t)m*512 + (k - 512);
    } else {
        return A0 + (size_t)m*512 + k;
    }
}

template<int MODE, int KD, bool OUTHALF, bool DOSILU>
__global__ void __launch_bounds__(512, 2) gemm_cp(
        const __half* __restrict__ A0, const __half* __restrict__ A1,
        const __half* __restrict__ W,  const float* __restrict__ bias,
        float* __restrict__ Cf, __half* __restrict__ Ch)
{
    extern __shared__ __half smem[];
    const unsigned sA = smem_u32(smem);
    const unsigned sB = sA + NSTAGE*ABYTES;

    const int tid  = threadIdx.x;
    const int lane = tid & 31;
    const int wid  = tid >> 5;           // 0..15
    const int g    = lane >> 2;
    const int cq   = lane & 3;
    const int mw   = (wid & 3) * 32;     // warp M offset (4 groups)
    const int nw   = (wid >> 2) * 32;    // warp N offset (4 groups)

    const int blockRow = blockIdx.y * 128;
    const int blockCol = blockIdx.x * 128;
    const int b_batch  = blockRow >> 14;
    const int i_idx    = (blockRow & 16383) >> 7;

    constexpr int NST = (KD + 31) / 32;

    // ldmatrix per-lane address components
    const int rowA_l = lane & 15;
    const int kA_l   = (lane >> 4) << 3;
    const int rowB_l = (lane & 7) + ((lane >> 3) & 1) * 8;
    const int nB_l   = (lane >> 4) << 3;

    float acc[2][4][4];                  // 32 regs: 2 m-tiles x 4 n8-tiles
    #pragma unroll
    for (int i = 0; i < 2; i++)
        #pragma unroll
        for (int j = 0; j < 4; j++)
            #pragma unroll
            for (int r = 0; r < 4; r++) acc[i][j][r] = 0.f;

    // ---- async stage issue: 512 threads -> 1 A-chunk + 1 B-chunk each
    auto issue = [&](int s){
        if (s < NST) {
            const int k0 = s*32, buf = s & (NSTAGE-1);
            {
                int row = tid >> 2, kc = (tid & 3)*8;
                cp16(sA + buf*ABYTES + (row*ASTRIDE + kc)*2,
                     srcA<MODE>(blockRow + row, k0 + kc, A0, A1, b_batch, i_idx));
            }
            {
                int row = tid >> 4, nc = (tid & 15)*8;
                cp16(sB + buf*BBYTES + (row*BSTRIDE + nc)*2,
                     W + (size_t)(k0 + row)*512 + blockCol + nc);
            }
        }
        CP_COMMIT();
    };

    issue(0); issue(1); issue(2);

    for (int s = 0; s < NST; s++) {
        CP_WAIT2();
        __syncthreads();                 // single barrier per stage
        issue(s + 3);                    // refill overlapped with compute

        const unsigned baseA = sA + (s & (NSTAGE-1))*ABYTES;
        const unsigned baseB = sB + (s & (NSTAGE-1))*BBYTES;
        #pragma unroll
        for (int kb = 0; kb < 32; kb += 16) {
            unsigned a[2][4], b[2][4];
            #pragma unroll
            for (int mt = 0; mt < 2; mt++) {
                unsigned addr = baseA + ((mw + mt*16 + rowA_l)*ASTRIDE + kb + kA_l)*2;
                asm volatile("ldmatrix.sync.aligned.m8n8.x4.shared.b16 {%0,%1,%2,%3}, [%4];"
                    : "=r"(a[mt][0]), "=r"(a[mt][1]), "=r"(a[mt][2]), "=r"(a[mt][3])
                    : "r"(addr));
            }
            #pragma unroll
            for (int ng = 0; ng < 2; ng++) {
                unsigned addr = baseB + ((kb + rowB_l)*BSTRIDE + nw + ng*16 + nB_l)*2;
                asm volatile("ldmatrix.sync.aligned.m8n8.x4.trans.shared.b16 {%0,%1,%2,%3}, [%4];"
                    : "=r"(b[ng][0]), "=r"(b[ng][1]), "=r"(b[ng][2]), "=r"(b[ng][3])
                    : "r"(addr));
            }
            #pragma unroll
            for (int mt = 0; mt < 2; mt++)
                #pragma unroll
                for (int ng = 0; ng < 2; ng++)
                    #pragma unroll
                    for (int h = 0; h < 2; h++) {
                        float* c = acc[mt][ng*2 + h];
                        asm volatile(
                            "mma.sync.aligned.m16n8k16.row.col.f32.f16.f16.f32 "
                            "{%0,%1,%2,%3}, {%4,%5,%6,%7}, {%8,%9}, {%0,%1,%2,%3};"
                            : "+f"(c[0]), "+f"(c[1]), "+f"(c[2]), "+f"(c[3])
                            : "r"(a[mt][0]), "r"(a[mt][1]), "r"(a[mt][2]), "r"(a[mt][3]),
                              "r"(b[ng][2*h]), "r"(b[ng][2*h+1]));
                    }
        }
    }

    // ---- epilogue
    #pragma unroll
    for (int mt = 0; mt < 2; mt++) {
        const int r0 = blockRow + mw + mt*16 + g;
        #pragma unroll
        for (int nt = 0; nt < 4; nt++) {
            const int c0 = blockCol + nw + nt*8 + 2*cq;
            const float bb0 = bias[c0], bb1 = bias[c0 + 1];
            float x0 = acc[mt][nt][0] + bb0;
            float x1 = acc[mt][nt][1] + bb1;
            float x2 = acc[mt][nt][2] + bb0;
            float x3 = acc[mt][nt][3] + bb1;
            if (DOSILU) { x0 = siluf(x0); x1 = siluf(x1); x2 = siluf(x2); x3 = siluf(x3); }
            if (OUTHALF) {
                *(__half2*)&Ch[(size_t)r0*512 + c0]     = __floats2half2_rn(x0, x1);
                *(__half2*)&Ch[(size_t)(r0+8)*512 + c0] = __floats2half2_rn(x2, x3);
            } else {
                *(float2*)&Cf[(size_t)r0*512 + c0]      = make_float2(x0, x1);
                *(float2*)&Cf[(size_t)(r0+8)*512 + c0]  = make_float2(x2, x3);
            }
        }
    }
}

// ---------------------------------------------------------------------------
// Merged converter: one launch (keeps ncu window on the GEMMs)
// ---------------------------------------------------------------------------
__global__ void k_conv_all(const float* __restrict__ e_f,
                           const float* __restrict__ W_epe,
                           const float* __restrict__ W_ev1,
                           const float* __restrict__ W_ev2,
                           const float* __restrict__ t_pe,
                           __half* __restrict__ efh, __half* __restrict__ wepeh,
                           __half* __restrict__ wev1h, __half* __restrict__ wev2h,
                           __half* __restrict__ tpeh)
{
    const int tid = blockIdx.x*256 + threadIdx.x;
    const int nthr = gridDim.x*256;

    for (size_t i = (size_t)tid*4; i < (size_t)M_BIG*E_IN; i += (size_t)nthr*4) {
        float4 v = *(const float4*)&e_f[i];
        *(__half2*)&efh[i]   = __floats2half2_rn(v.x, v.y);
        *(__half2*)&efh[i+2] = __floats2half2_rn(v.z, v.w);
    }
    for (int i = tid; i < 640*512; i += nthr) {
        int k = i >> 9;
        wepeh[i] = (k < 612) ? __float2half(W_epe[i]) : __float2half(0.f);
    }
    for (int i = tid; i < 1024*512; i += nthr)
        wev1h[i] = __float2half(W_ev1[i]);
    for (int i = tid; i < 512*512; i += nthr)
        wev2h[i] = __float2half(W_ev2[i]);
    for (int i = tid; i < BB*128; i += nthr) {
        int b = i >> 7, r = i & 127;
        tpeh[i] = (r < 100) ? __float2half(t_pe[b*100 + r]) : __float2half(0.f);
    }
}

// ---------------------------------------------------------------------------
// Kernel 1: v = silu([v_f, p_pe, t_pe] @ W_vpe + b)  (also writes g_vh)
// ---------------------------------------------------------------------------
__global__ void k_vpe(const float* __restrict__ v_f, const float* __restrict__ p_pe,
                      const float* __restrict__ t_pe, const float* __restrict__ W,
                      const float* __restrict__ bias)
{
    __shared__ float s_in[556];
    int m = blockIdx.x;
    int b = m >> 7;
    for (int kk = threadIdx.x; kk < 556; kk += 256) {
        float x;
        if      (kk < 256) x = v_f[m*256 + kk];
        else if (kk < 456) x = p_pe[m*200 + (kk-256)];
        else               x = t_pe[b*100 + (kk-456)];
        s_in[kk] = x;
    }
    __syncthreads();
    int n = threadIdx.x;
    float acc = bias[n];
    #pragma unroll 4
    for (int kk = 0; kk < 556; kk++) acc = fmaf(s_in[kk], W[kk*256 + n], acc);
    float s = siluf(acc);
    g_v[m*256 + n]  = s;
    g_vh[m*256 + n] = __float2half(s);
}

// ---------------------------------------------------------------------------
// Kernel 2: q = v@Wq+b, k = v@Wk+b, self = silu(v@Ws+b)
// ---------------------------------------------------------------------------
__global__ void k_qks(const float* __restrict__ Wq, const float* __restrict__ bq,
                      const float* __restrict__ Wk, const float* __restrict__ bk,
                      const float* __restrict__ Ws, const float* __restrict__ bs)
{
    __shared__ float s_v[256];
    int m = blockIdx.x;
    for (int kk = threadIdx.x; kk < 256; kk += 512) s_v[kk] = g_v[m*256 + kk];
    __syncthreads();
    int n = threadIdx.x;
    float aq = bq[n], ak = bk[n], as_ = bs[n];
    #pragma unroll 4
    for (int kk = 0; kk < 256; kk++) {
        float x = s_v[kk];
        aq  = fmaf(x, Wq[kk*512 + n], aq);
        ak  = fmaf(x, Wk[kk*512 + n], ak);
        as_ = fmaf(x, Ws[kk*512 + n], as_);
    }
    g_q[m*512 + n]    = aq;
    g_k[m*512 + n]    = ak;
    g_self[m*512 + n] = siluf(as_);
}

// ---------------------------------------------------------------------------
// Attention + aggregation
// ---------------------------------------------------------------------------
__global__ void k_attn(const float* __restrict__ e_mask, const float* __restrict__ e_value)
{
    __shared__ float s_q[512];
    __shared__ float s_att[128*32];
    __shared__ float s_inv[32];

    int m = blockIdx.x;
    int b = m >> 7;

    for (int c = threadIdx.x; c < 512; c += 256) s_q[c] = g_q[m*512 + c];
    __syncthreads();

    const float scale = 0.14433756729740643f;   // 1/sqrt(48)
    for (int idx = threadIdx.x; idx < 4096; idx += 256) {
        int j = idx >> 5, g = idx & 31;
        const float* kr = &g_k[((b<<7) + j)*512 + (g<<4)];
        float s = 0.f;
        #pragma unroll
        for (int h = 0; h < 16; h++) s = fmaf(s_q[(g<<4) + h], kr[h], s);
        s_att[(j<<5) + g] = sigmf(s * scale) * e_mask[(m<<7) + j];
    }
    __syncthreads();

    if (threadIdx.x < 32) {
        int g = threadIdx.x;
        float s = 0.f;
        #pragma unroll 8
        for (int j = 0; j < 128; j++) s += s_att[(j<<5) + g];
        s_inv[g] = 1.f / (s + 1e-6f);
    }
    __syncthreads();

    for (int c = threadIdx.x; c < 512; c += 256) {
        int g = c >> 4;
        const float* ev = e_value + ((size_t)m*128)*512 + c;
        float acc = 0.f;
        #pragma unroll 4
        for (int j = 0; j < 128; j++) acc = fmaf(s_att[(j<<5) + g], ev[(size_t)j*512], acc);
        g_v2[m*512 + c] = acc * s_inv[g] + g_self[m*512 + c];
    }
}

__global__ void k_pool(const float* __restrict__ v_mask)
{
    int idx = blockIdx.x*256 + threadIdx.x;
    if (idx >= BB*512) return;
    int b = idx >> 9, c = idx & 511;
    float mx = -3.4e38f;
    for (int i = 0; i < 128; i++) {
        float pen = 1e9f * (1.f - v_mask[(b<<7) + i]);
        mx = fmaxf(mx, g_v2[((b<<7) + i)*512 + c] - pen);
    }
    g_pool[idx] = mx;
}

__global__ void k_out(const float* __restrict__ W, const float* __restrict__ bias,
                      float* __restrict__ out)
{
    __shared__ float s_in[1024];
    int m = blockIdx.x;
    int b = m >> 7;
    for (int kk = threadIdx.x; kk < 512; kk += 256) {
        s_in[kk]       = g_v2[m*512 + kk];
        s_in[512 + kk] = g_pool[(b<<9) + kk];
    }
    __syncthreads();
    int n = threadIdx.x;
    float acc = bias[n];
    #pragma unroll 4
    for (int kk = 0; kk < 1024; kk++) acc = fmaf(s_in[kk], W[kk*256 + n], acc);
    out[m*256 + n] = siluf(acc);
}

// ---------------------------------------------------------------------------
// Launch
// ---------------------------------------------------------------------------
extern "C" void kernel_launch(void* const* d_in, const int* in_sizes, int n_in,
                              void* d_out, int out_size)
{
    const float* v_f    = (const float*)d_in[0];
    const float* e_f    = (const float*)d_in[1];
    const float* p_pe   = (const float*)d_in[2];
    const float* t_pe   = (const float*)d_in[3];
    const float* e_mask = (const float*)d_in[4];
    const float* v_mask = (const float*)d_in[5];
    const float* W_vpe  = (const float*)d_in[6];
    const float* b_vpe  = (const float*)d_in[7];
    const float* W_epe  = (const float*)d_in[8];
    const float* b_epe  = (const float*)d_in[9];
    const float* W_ev1  = (const float*)d_in[10];
    const float* b_ev1  = (const float*)d_in[11];
    const float* W_ev2  = (const float*)d_in[12];
    const float* b_ev2  = (const float*)d_in[13];
    const float* W_q    = (const float*)d_in[14];
    const float* b_q    = (const float*)d_in[15];
    const float* W_k    = (const float*)d_in[16];
    const float* b_k    = (const float*)d_in[17];
    const float* W_self = (const float*)d_in[18];
    const float* b_self = (const float*)d_in[19];
    const float* W_out  = (const float*)d_in[20];
    const float* b_out  = (const float*)d_in[21];

    float* out_v = (float*)d_out;                       // (4,128,256)
    float* out_e = (float*)d_out + NROWS*V_OUT;         // (4,16384,512)

    __half *pefh, *peh, *phh, *pvh, *ptpeh, *pwepeh, *pwev1h, *pwev2h;
    cudaGetSymbolAddress((void**)&pefh,   g_efh);
    cudaGetSymbolAddress((void**)&peh,    g_eh);
    cudaGetSymbolAddress((void**)&phh,    g_hh);
    cudaGetSymbolAddress((void**)&pvh,    g_vh);
    cudaGetSymbolAddress((void**)&ptpeh,  g_tpeh);
    cudaGetSymbolAddress((void**)&pwepeh, g_wepeh);
    cudaGetSymbolAddress((void**)&pwev1h, g_wev1h);
    cudaGetSymbolAddress((void**)&pwev2h, g_wev2h);

    cudaFuncSetAttribute(gemm_cp<0, 612,  true,  true >, cudaFuncAttributeMaxDynamicSharedMemorySize, SMEM_SZ);
    cudaFuncSetAttribute(gemm_cp<1, 1024, true,  true >, cudaFuncAttributeMaxDynamicSharedMemorySize, SMEM_SZ);
    cudaFuncSetAttribute(gemm_cp<2, 512,  false, false>, cudaFuncAttributeMaxDynamicSharedMemorySize, SMEM_SZ);

    dim3 gemm_grid(4, M_BIG/128);                       // (4, 512)

    // single merged converter launch (keeps ncu window on the GEMMs)
    k_conv_all<<<592, 256>>>(e_f, W_epe, W_ev1, W_ev2, t_pe,
                             pefh, pwepeh, pwev1h, pwev2h, ptpeh);

    k_vpe<<<NROWS, 256>>>(v_f, p_pe, t_pe, W_vpe, b_vpe);
    k_qks<<<NROWS, 512>>>(W_q, b_q, W_k, b_k, W_self, b_self);

    gemm_cp<0, 612,  true,  true ><<<gemm_grid, 512, SMEM_SZ>>>(pefh, ptpeh, pwepeh, b_epe, nullptr, peh);
    gemm_cp<1, 1024, true,  true ><<<gemm_grid, 512, SMEM_SZ>>>(pvh,  peh,   pwev1h, b_ev1, nullptr, phh);
    gemm_cp<2, 512,  false, false><<<gemm_grid, 512, SMEM_SZ>>>(phh,  nullptr, pwev2h, b_ev2, out_e, nullptr);

    k_attn<<<NROWS, 256>>>(e_mask, out_e);
    k_pool<<<(BB*512 + 255)/256, 256>>>(v_mask);
    k_out<<<NROWS, 256>>>(W_out, b_out, out_v);
}

// round 16
// speedup vs baseline: 1.4498x; 1.4498x over previous
#include <cuda_runtime.h>
#include <cuda_fp16.h>
#include <math.h>

// Problem constants
#define BB    4
#define KDIM  128
#define V_IN  256
#define E_IN  512
#define E_OUT 512
#define V_OUT 256
#define P_PE  200
#define T_PE  100
#define NROWS (BB*KDIM)        // 512
#define M_BIG (BB*KDIM*KDIM)   // 65536

// Scratch (device globals -- allocation-free per harness rules)
__device__ float  g_v[NROWS*V_IN];
__device__ float  g_q[NROWS*E_OUT];
__device__ float  g_k[NROWS*E_OUT];
__device__ float  g_self[NROWS*E_OUT];
__device__ float  g_v2[NROWS*E_OUT];
__device__ float  g_pool[BB*E_OUT];

// fp16-at-rest GEMM operands
__device__ __half g_vh[NROWS*V_IN];
__device__ __half g_efh[(size_t)M_BIG*E_IN];     // e_f as half (67 MB)
__device__ __half g_eh [(size_t)M_BIG*E_IN];     // silu(epe) half
__device__ __half g_hh [(size_t)M_BIG*E_OUT];    // silu(ev1) half
__device__ __half g_tpeh[BB*128];                // t_pe padded to 128
__device__ __half g_wepeh[640*512];              // W_epe padded 612->640 rows
__device__ __half g_wev1h[1024*512];
__device__ __half g_wev2h[512*512];

__device__ __forceinline__ float siluf(float x){ return x / (1.f + __expf(-x)); }
__device__ __forceinline__ float sigmf(float x){ return 1.f / (1.f + __expf(-x)); }

__device__ __forceinline__ unsigned smem_u32(const void* p){
    unsigned r;
    asm("{ .reg .u64 t; cvta.to.shared.u64 t, %1; cvt.u32.u64 %0, t; }" : "=r"(r) : "l"(p));
    return r;
}

// ===========================================================================
// FP16 mma.sync GEMM (R5-proven structure): register-staged double buffer,
// fp16-at-rest operands (uint4 = 8-half global loads, no in-loop cvt).
// CTA tile 128x128, BK=32, 8 warps (2x4), warp tile 64x32.
// A smem [m][k] stride 40 halves; B smem [k][n] stride 136 halves.
// MODE 0 (epe): A = [g_efh(512)|g_tpeh(128 pad)], KD=640 (padded), silu, half out
// MODE 1 (ev1): A = [v_i(256)|v_j(256)|g_eh(512)], KD=1024, silu, half out
// MODE 2 (ev2): A = g_hh, KD=512, no act, fp32 out
// ===========================================================================
#define ASTRIDE 40
#define BSTRIDE 136
#define ABUF (128*ASTRIDE)
#define BBUF (32*BSTRIDE)

template<int MODE>
__device__ __forceinline__ const __half* srcA(int m, int k,
                                              const __half* __restrict__ A0,
                                              const __half* __restrict__ A1,
                                              int b_batch, int i_idx)
{
    if (MODE == 0) {
        return (k < 512) ? A0 + (size_t)m*512 + k
                         : A1 + b_batch*128 + (k - 512);
    } else if (MODE == 1) {
        if (k < 256) return A0 + ((b_batch<<7) + i_idx)*256 + k;
        if (k < 512) return A0 + ((b_batch<<7) + (m & 127))*256 + (k - 256);
        return A1 + (size_t)m*512 + (k - 512);
    } else {
        return A0 + (size_t)m*512 + k;
    }
}

template<int MODE, int KD, bool OUTHALF, bool DOSILU>
__global__ void __launch_bounds__(256, 2) gemm_r5(
        const __half* __restrict__ A0, const __half* __restrict__ A1,
        const __half* __restrict__ W,  const float* __restrict__ bias,
        float* __restrict__ Cf, __half* __restrict__ Ch)
{
    __shared__ __half As[2*ABUF];
    __shared__ __half Bs[2*BBUF];

    const int tid  = threadIdx.x;
    const int lane = tid & 31;
    const int wid  = tid >> 5;
    const int g    = lane >> 2;
    const int cq   = lane & 3;
    const int mw   = (wid >> 2) * 64;
    const int nw   = (wid & 3) * 32;

    const int blockRow = blockIdx.y * 128;
    const int blockCol = blockIdx.x * 128;
    const int b_batch  = blockRow >> 14;
    const int i_idx    = (blockRow & 16383) >> 7;

    constexpr int NST = (KD + 31) / 32;

    // staging coords: A chunks (row, 8-half col), B chunks
    const int ar0 = tid >> 2,  ak0 = (tid & 3)*8;      // chunk tid
    const int ar1 = (tid + 256) >> 2, ak1 = ((tid + 256) & 3)*8;
    const int br0 = tid >> 4,  bn0 = (tid & 15)*8;
    const int br1 = (tid + 256) >> 4, bn1 = ((tid + 256) & 15)*8;

    const unsigned sA = smem_u32(As);
    const unsigned sB = smem_u32(Bs);

    // ldmatrix per-lane address components
    const int rowA_l = lane & 15;
    const int kA_l   = (lane >> 4) << 3;
    const int rowB_l = (lane & 7) + ((lane >> 3) & 1) * 8;
    const int nB_l   = (lane >> 4) << 3;

    float acc[4][4][4];
    #pragma unroll
    for (int i = 0; i < 4; i++)
        #pragma unroll
        for (int j = 0; j < 4; j++)
            #pragma unroll
            for (int r = 0; r < 4; r++) acc[i][j][r] = 0.f;

    // ---- prologue: stage tile 0 into buf 0 (direct global->smem)
    {
        *(uint4*)&As[ar0*ASTRIDE + ak0] = *(const uint4*)srcA<MODE>(blockRow + ar0, ak0, A0, A1, b_batch, i_idx);
        *(uint4*)&As[ar1*ASTRIDE + ak1] = *(const uint4*)srcA<MODE>(blockRow + ar1, ak1, A0, A1, b_batch, i_idx);
        *(uint4*)&Bs[br0*BSTRIDE + bn0] = *(const uint4*)&W[(size_t)br0*512 + blockCol + bn0];
        *(uint4*)&Bs[br1*BSTRIDE + bn1] = *(const uint4*)&W[(size_t)br1*512 + blockCol + bn1];
    }
    __syncthreads();

    uint4 aR[2], bR[2];
    for (int s = 0; s < NST; s++) {
        const int cur = s & 1, nxt = cur ^ 1;

        // prefetch next tile into registers
        if (s + 1 < NST) {
            const int k0n = (s + 1) * 32;
            aR[0] = *(const uint4*)srcA<MODE>(blockRow + ar0, k0n + ak0, A0, A1, b_batch, i_idx);
            aR[1] = *(const uint4*)srcA<MODE>(blockRow + ar1, k0n + ak1, A0, A1, b_batch, i_idx);
            bR[0] = *(const uint4*)&W[(size_t)(k0n + br0)*512 + blockCol + bn0];
            bR[1] = *(const uint4*)&W[(size_t)(k0n + br1)*512 + blockCol + bn1];
        }

        // compute on current buffer: 2 ksteps of k16
        const unsigned baseA = sA + cur*(ABUF*2);
        const unsigned baseB = sB + cur*(BBUF*2);
        #pragma unroll
        for (int kb = 0; kb < 32; kb += 16) {
            unsigned a[4][4], b[2][4];
            #pragma unroll
            for (int ms = 0; ms < 4; ms++) {
                unsigned addr = baseA + ((mw + ms*16 + rowA_l)*ASTRIDE + kb + kA_l)*2;
                asm volatile("ldmatrix.sync.aligned.m8n8.x4.shared.b16 {%0,%1,%2,%3}, [%4];"
                    : "=r"(a[ms][0]), "=r"(a[ms][1]), "=r"(a[ms][2]), "=r"(a[ms][3])
                    : "r"(addr));
            }
            #pragma unroll
            for (int ng = 0; ng < 2; ng++) {
                unsigned addr = baseB + ((kb + rowB_l)*BSTRIDE + nw + ng*16 + nB_l)*2;
                asm volatile("ldmatrix.sync.aligned.m8n8.x4.trans.shared.b16 {%0,%1,%2,%3}, [%4];"
                    : "=r"(b[ng][0]), "=r"(b[ng][1]), "=r"(b[ng][2]), "=r"(b[ng][3])
                    : "r"(addr));
            }
            #pragma unroll
            for (int ms = 0; ms < 4; ms++)
                #pragma unroll
                for (int ng = 0; ng < 2; ng++)
                    #pragma unroll
                    for (int h = 0; h < 2; h++) {
                        float* c = acc[ms][ng*2 + h];
                        asm volatile(
                            "mma.sync.aligned.m16n8k16.row.col.f32.f16.f16.f32 "
                            "{%0,%1,%2,%3}, {%4,%5,%6,%7}, {%8,%9}, {%0,%1,%2,%3};"
                            : "+f"(c[0]), "+f"(c[1]), "+f"(c[2]), "+f"(c[3])
                            : "r"(a[ms][0]), "r"(a[ms][1]), "r"(a[ms][2]), "r"(a[ms][3]),
                              "r"(b[ng][2*h]), "r"(b[ng][2*h+1]));
                    }
        }

        // store prefetched tile into next buffer
        if (s + 1 < NST) {
            *(uint4*)&As[nxt*ABUF + ar0*ASTRIDE + ak0] = aR[0];
            *(uint4*)&As[nxt*ABUF + ar1*ASTRIDE + ak1] = aR[1];
            *(uint4*)&Bs[nxt*BBUF + br0*BSTRIDE + bn0] = bR[0];
            *(uint4*)&Bs[nxt*BBUF + br1*BSTRIDE + bn1] = bR[1];
        }
        __syncthreads();
    }

    // ---- epilogue
    #pragma unroll
    for (int ms = 0; ms < 4; ms++) {
        const int r0 = blockRow + mw + ms*16 + g;
        #pragma unroll
        for (int ns = 0; ns < 4; ns++) {
            const int c0 = blockCol + nw + ns*8 + 2*cq;
            const float bb0 = bias[c0], bb1 = bias[c0 + 1];
            float x0 = acc[ms][ns][0] + bb0;
            float x1 = acc[ms][ns][1] + bb1;
            float x2 = acc[ms][ns][2] + bb0;
            float x3 = acc[ms][ns][3] + bb1;
            if (DOSILU) { x0 = siluf(x0); x1 = siluf(x1); x2 = siluf(x2); x3 = siluf(x3); }
            if (OUTHALF) {
                *(__half2*)&Ch[(size_t)r0*512 + c0]     = __floats2half2_rn(x0, x1);
                *(__half2*)&Ch[(size_t)(r0+8)*512 + c0] = __floats2half2_rn(x2, x3);
            } else {
                *(float2*)&Cf[(size_t)r0*512 + c0]      = make_float2(x0, x1);
                *(float2*)&Cf[(size_t)(r0+8)*512 + c0]  = make_float2(x2, x3);
            }
        }
    }
}

// ---------------------------------------------------------------------------
// Merged converter: one launch (keeps ncu window on the GEMMs)
// ---------------------------------------------------------------------------
__global__ void k_conv_all(const float* __restrict__ e_f,
                           const float* __restrict__ W_epe,
                           const float* __restrict__ W_ev1,
                           const float* __restrict__ W_ev2,
                           const float* __restrict__ t_pe,
                           __half* __restrict__ efh, __half* __restrict__ wepeh,
                           __half* __restrict__ wev1h, __half* __restrict__ wev2h,
                           __half* __restrict__ tpeh)
{
    const int tid = blockIdx.x*256 + threadIdx.x;
    const int nthr = gridDim.x*256;

    for (size_t i = (size_t)tid*4; i < (size_t)M_BIG*E_IN; i += (size_t)nthr*4) {
        float4 v = *(const float4*)&e_f[i];
        *(__half2*)&efh[i]   = __floats2half2_rn(v.x, v.y);
        *(__half2*)&efh[i+2] = __floats2half2_rn(v.z, v.w);
    }
    for (int i = tid; i < 640*512; i += nthr) {
        int k = i >> 9;
        wepeh[i] = (k < 612) ? __float2half(W_epe[i]) : __float2half(0.f);
    }
    for (int i = tid; i < 1024*512; i += nthr)
        wev1h[i] = __float2half(W_ev1[i]);
    for (int i = tid; i < 512*512; i += nthr)
        wev2h[i] = __float2half(W_ev2[i]);
    for (int i = tid; i < BB*128; i += nthr) {
        int b = i >> 7, r = i & 127;
        tpeh[i] = (r < 100) ? __float2half(t_pe[b*100 + r]) : __float2half(0.f);
    }
}

// ---------------------------------------------------------------------------
// Kernel 1: v = silu([v_f, p_pe, t_pe] @ W_vpe + b)  (also writes g_vh)
// ---------------------------------------------------------------------------
__global__ void k_vpe(const float* __restrict__ v_f, const float* __restrict__ p_pe,
                      const float* __restrict__ t_pe, const float* __restrict__ W,
                      const float* __restrict__ bias)
{
    __shared__ float s_in[556];
    int m = blockIdx.x;
    int b = m >> 7;
    for (int kk = threadIdx.x; kk < 556; kk += 256) {
        float x;
        if      (kk < 256) x = v_f[m*256 + kk];
        else if (kk < 456) x = p_pe[m*200 + (kk-256)];
        else               x = t_pe[b*100 + (kk-456)];
        s_in[kk] = x;
    }
    __syncthreads();
    int n = threadIdx.x;
    float acc = bias[n];
    #pragma unroll 4
    for (int kk = 0; kk < 556; kk++) acc = fmaf(s_in[kk], W[kk*256 + n], acc);
    float s = siluf(acc);
    g_v[m*256 + n]  = s;
    g_vh[m*256 + n] = __float2half(s);
}

// ---------------------------------------------------------------------------
// Kernel 2: q = v@Wq+b, k = v@Wk+b, self = silu(v@Ws+b)
// ---------------------------------------------------------------------------
__global__ void k_qks(const float* __restrict__ Wq, const float* __restrict__ bq,
                      const float* __restrict__ Wk, const float* __restrict__ bk,
                      const float* __restrict__ Ws, const float* __restrict__ bs)
{
    __shared__ float s_v[256];
    int m = blockIdx.x;
    for (int kk = threadIdx.x; kk < 256; kk += 512) s_v[kk] = g_v[m*256 + kk];
    __syncthreads();
    int n = threadIdx.x;
    float aq = bq[n], ak = bk[n], as_ = bs[n];
    #pragma unroll 4
    for (int kk = 0; kk < 256; kk++) {
        float x = s_v[kk];
        aq  = fmaf(x, Wq[kk*512 + n], aq);
        ak  = fmaf(x, Wk[kk*512 + n], ak);
        as_ = fmaf(x, Ws[kk*512 + n], as_);
    }
    g_q[m*512 + n]    = aq;
    g_k[m*512 + n]    = ak;
    g_self[m*512 + n] = siluf(as_);
}

// ---------------------------------------------------------------------------
// Attention + aggregation
// ---------------------------------------------------------------------------
__global__ void k_attn(const float* __restrict__ e_mask, const float* __restrict__ e_value)
{
    __shared__ float s_q[512];
    __shared__ float s_att[128*32];
    __shared__ float s_inv[32];

    int m = blockIdx.x;
    int b = m >> 7;

    for (int c = threadIdx.x; c < 512; c += 256) s_q[c] = g_q[m*512 + c];
    __syncthreads();

    const float scale = 0.14433756729740643f;   // 1/sqrt(48)
    for (int idx = threadIdx.x; idx < 4096; idx += 256) {
        int j = idx >> 5, g = idx & 31;
        const float* kr = &g_k[((b<<7) + j)*512 + (g<<4)];
        float s = 0.f;
        #pragma unroll
        for (int h = 0; h < 16; h++) s = fmaf(s_q[(g<<4) + h], kr[h], s);
        s_att[(j<<5) + g] = sigmf(s * scale) * e_mask[(m<<7) + j];
    }
    __syncthreads();

    if (threadIdx.x < 32) {
        int g = threadIdx.x;
        float s = 0.f;
        #pragma unroll 8
        for (int j = 0; j < 128; j++) s += s_att[(j<<5) + g];
        s_inv[g] = 1.f / (s + 1e-6f);
    }
    __syncthreads();

    for (int c = threadIdx.x; c < 512; c += 256) {
        int g = c >> 4;
        const float* ev = e_value + ((size_t)m*128)*512 + c;
        float acc = 0.f;
        #pragma unroll 4
        for (int j = 0; j < 128; j++) acc = fmaf(s_att[(j<<5) + g], ev[(size_t)j*512], acc);
        g_v2[m*512 + c] = acc * s_inv[g] + g_self[m*512 + c];
    }
}

__global__ void k_pool(const float* __restrict__ v_mask)
{
    int idx = blockIdx.x*256 + threadIdx.x;
    if (idx >= BB*512) return;
    int b = idx >> 9, c = idx & 511;
    float mx = -3.4e38f;
    for (int i = 0; i < 128; i++) {
        float pen = 1e9f * (1.f - v_mask[(b<<7) + i]);
        mx = fmaxf(mx, g_v2[((b<<7) + i)*512 + c] - pen);
    }
    g_pool[idx] = mx;
}

__global__ void k_out(const float* __restrict__ W, const float* __restrict__ bias,
                      float* __restrict__ out)
{
    __shared__ float s_in[1024];
    int m = blockIdx.x;
    int b = m >> 7;
    for (int kk = threadIdx.x; kk < 512; kk += 256) {
        s_in[kk]       = g_v2[m*512 + kk];
        s_in[512 + kk] = g_pool[(b<<9) + kk];
    }
    __syncthreads();
    int n = threadIdx.x;
    float acc = bias[n];
    #pragma unroll 4
    for (int kk = 0; kk < 1024; kk++) acc = fmaf(s_in[kk], W[kk*256 + n], acc);
    out[m*256 + n] = siluf(acc);
}

// ---------------------------------------------------------------------------
// Launch
// ---------------------------------------------------------------------------
extern "C" void kernel_launch(void* const* d_in, const int* in_sizes, int n_in,
                              void* d_out, int out_size)
{
    const float* v_f    = (const float*)d_in[0];
    const float* e_f    = (const float*)d_in[1];
    const float* p_pe   = (const float*)d_in[2];
    const float* t_pe   = (const float*)d_in[3];
    const float* e_mask = (const float*)d_in[4];
    const float* v_mask = (const float*)d_in[5];
    const float* W_vpe  = (const float*)d_in[6];
    const float* b_vpe  = (const float*)d_in[7];
    const float* W_epe  = (const float*)d_in[8];
    const float* b_epe  = (const float*)d_in[9];
    const float* W_ev1  = (const float*)d_in[10];
    const float* b_ev1  = (const float*)d_in[11];
    const float* W_ev2  = (const float*)d_in[12];
    const float* b_ev2  = (const float*)d_in[13];
    const float* W_q    = (const float*)d_in[14];
    const float* b_q    = (const float*)d_in[15];
    const float* W_k    = (const float*)d_in[16];
    const float* b_k    = (const float*)d_in[17];
    const float* W_self = (const float*)d_in[18];
    const float* b_self = (const float*)d_in[19];
    const float* W_out  = (const float*)d_in[20];
    const float* b_out  = (const float*)d_in[21];

    float* out_v = (float*)d_out;                       // (4,128,256)
    float* out_e = (float*)d_out + NROWS*V_OUT;         // (4,16384,512)

    __half *pefh, *peh, *phh, *pvh, *ptpeh, *pwepeh, *pwev1h, *pwev2h;
    cudaGetSymbolAddress((void**)&pefh,   g_efh);
    cudaGetSymbolAddress((void**)&peh,    g_eh);
    cudaGetSymbolAddress((void**)&phh,    g_hh);
    cudaGetSymbolAddress((void**)&pvh,    g_vh);
    cudaGetSymbolAddress((void**)&ptpeh,  g_tpeh);
    cudaGetSymbolAddress((void**)&pwepeh, g_wepeh);
    cudaGetSymbolAddress((void**)&pwev1h, g_wev1h);
    cudaGetSymbolAddress((void**)&pwev2h, g_wev2h);

    dim3 gemm_grid(4, M_BIG/128);                       // (4, 512)

    // single merged converter launch (keeps ncu window on the GEMMs)
    k_conv_all<<<592, 256>>>(e_f, W_epe, W_ev1, W_ev2, t_pe,
                             pefh, pwepeh, pwev1h, pwev2h, ptpeh);

    k_vpe<<<NROWS, 256>>>(v_f, p_pe, t_pe, W_vpe, b_vpe);
    k_qks<<<NROWS, 512>>>(W_q, b_q, W_k, b_k, W_self, b_self);

    gemm_r5<0, 640,  true,  true ><<<gemm_grid, 256>>>(pefh, ptpeh, pwepeh, b_epe, nullptr, peh);
    gemm_r5<1, 1024, true,  true ><<<gemm_grid, 256>>>(pvh,  peh,   pwev1h, b_ev1, nullptr, phh);
    gemm_r5<2, 512,  false, false><<<gemm_grid, 256>>>(phh,  nullptr, pwev2h, b_ev2, out_e, nullptr);

    k_attn<<<NROWS, 256>>>(e_mask, out_e);
    k_pool<<<(BB*512 + 255)/256, 256>>>(v_mask);
    k_out<<<NROWS, 256>>>(W_out, b_out, out_v);
}